// round 9
// baseline (speedup 1.0000x reference)
#include <cuda_runtime.h>
#include <math_constants.h>

// Shapes (fixed by problem)
#define B 32
#define T 512
#define D 512
#define H 8
#define S 196
#define LAYER_ID 2
#define K_TOP 51   // int(0.1 * 512)
#define NBLK 16    // blocks per batch
#define CHUNK 32   // t's per block
#define NG 32      // partial groups (NBLK x 2 subgroups)

// Scratch (allocation-free rule: __device__ globals; zero-initialized)
__device__ float g_w[B * T];
__device__ float g_part[B][NG][S];
__device__ int   g_sync[B];

__device__ __forceinline__ float ldcg(const float* p) {
    float v; asm volatile("ld.global.cg.f32 %0, [%1];" : "=f"(v) : "l"(p));
    return v;
}

// ---------------------------------------------------------------------------
// Kernel 1: cosine weights. One warp handles TWO t-rows (12 LDG.128/thread),
// no smem, no syncthreads. grid (T/16, B), 256 threads.  [validated in R6]
// ---------------------------------------------------------------------------
__global__ __launch_bounds__(256) void k_weights(
    const float* __restrict__ fore,     // (B, D)
    const float* __restrict__ embed,    // (B, T, D)
    const int*   __restrict__ targets)  // (B, T+1) int32
{
    const int b    = blockIdx.y;
    const int lane = threadIdx.x & 31;
    const int warp = threadIdx.x >> 5;
    const int t0   = (blockIdx.x * 8 + warp) * 2;

    const float4* yrow = reinterpret_cast<const float4*>(fore + (size_t)b * D);
    const float4* x0   = reinterpret_cast<const float4*>(embed + ((size_t)b * T + t0) * D);
    const float4* x1   = x0 + D / 4;

    float4 yv[4], xa[4], xb[4];
#pragma unroll
    for (int i = 0; i < 4; i++) {
        yv[i] = __ldg(&yrow[lane + i * 32]);
        xa[i] = __ldg(&x0[lane + i * 32]);
        xb[i] = __ldg(&x1[lane + i * 32]);
    }

    float n0 = 0.f, n1 = 0.f, xs0 = 0.f, xs1 = 0.f, ys = 0.f;
#pragma unroll
    for (int i = 0; i < 4; i++) {
        float4 y = yv[i], a = xa[i], c = xb[i];
        ys  += y.x * y.x + y.y * y.y + y.z * y.z + y.w * y.w;
        n0  += a.x * y.x + a.y * y.y + a.z * y.z + a.w * y.w;
        xs0 += a.x * a.x + a.y * a.y + a.z * a.z + a.w * a.w;
        n1  += c.x * y.x + c.y * y.y + c.z * y.z + c.w * y.w;
        xs1 += c.x * c.x + c.y * c.y + c.z * c.z + c.w * c.w;
    }
#pragma unroll
    for (int o = 16; o; o >>= 1) {
        n0  += __shfl_xor_sync(0xffffffffu, n0,  o);
        n1  += __shfl_xor_sync(0xffffffffu, n1,  o);
        xs0 += __shfl_xor_sync(0xffffffffu, xs0, o);
        xs1 += __shfl_xor_sync(0xffffffffu, xs1, o);
        ys  += __shfl_xor_sync(0xffffffffu, ys,  o);
    }
    if (lane < 2) {
        const int t = t0 + lane;
        float num = lane ? n1 : n0;
        float xn2 = lane ? xs1 : xs0;
        float xn  = fmaxf(sqrtf(xn2), 1e-8f);
        float yn  = fmaxf(sqrtf(ys),  1e-8f);
        float w   = num / (xn * yn);
        int tv    = targets[b * (T + 1) + t];
        bool msk  = (t == 0) || (tv > 0);
        g_w[b * T + t] = msk ? w : -1.0f;
    }
}

// ---------------------------------------------------------------------------
// Kernel 2 (fused): grid (NBLK, B), 512 threads. Block c ranks ONLY its
// 32-t chunk: thread (tl = tid>>4, piece = tid&15) compares key[tl] against
// a disjoint 32-key slice, shuffle-reduced over the 16 piece lanes -> no
// atomics. Select rank<m, gather selected rows (2 s-subgroups), write
// partials; last-arriving block per b merges 32 partials + normalizes.
// ---------------------------------------------------------------------------
__global__ __launch_bounds__(512) void k_fused(
    const int*   __restrict__ targets,  // (B, T+1) int32
    const float* __restrict__ attns,    // (L, B, H, T, S)
    float*       __restrict__ out)      // (B, S)
{
    __shared__ unsigned long long keys[T];   // 4 KB
    __shared__ int   rank[CHUNK];
    __shared__ int   sl[CHUNK];
    __shared__ float slw[CHUNK];
    __shared__ int   s_last;
    __shared__ float rmin[256], rmax[256];
    __shared__ float s_mn, s_mx;

    const int c   = blockIdx.x;   // 0..NBLK-1
    const int b   = blockIdx.y;
    const int tid = threadIdx.x;  // 0..511

    // ---- Phase 1: keys (order-preserving map, index tie-break) + m
    float w = ldcg(&g_w[b * T + tid]);
    unsigned uf = __float_as_uint(w);
    uf = (uf & 0x80000000u) ? ~uf : (uf | 0x80000000u);
    keys[tid] = ((unsigned long long)uf << 32) | (unsigned)(T - 1 - tid);

    int tv  = targets[b * (T + 1) + tid];
    int cnt = __syncthreads_count((tid == 0) || (tv > 0));   // barrier #1
    int m   = (int)ceilf((float)cnt * 0.1f);
    m = m < K_TOP ? m : K_TOP;

    // ---- Phase 2: chunk-local rank counting, shuffle-combined (no atomics)
    {
        const int tl    = tid >> 4;                // 0..31  (t_local)
        const int piece = tid & 15;                // 0..15  (key slice)
        const unsigned long long mykey = keys[c * CHUNK + tl];
        const unsigned long long* kp = keys + piece * 32;
        int r = 0;
#pragma unroll
        for (int i = 0; i < 32; i++) r += (kp[i] > mykey);
        // sum over the 16 piece-lanes (lanes with same tl are contiguous 16)
#pragma unroll
        for (int o = 8; o; o >>= 1) r += __shfl_xor_sync(0xffffffffu, r, o);
        if (piece == 0) rank[tl] = r;
    }
    __syncthreads();                                          // barrier #2

    // ---- Phase 3: selected list for this chunk, t-order (deterministic)
    bool selme = (tid < CHUNK) && (rank[tid] < m);
    if (selme) {
        int pos = 0;
#pragma unroll
        for (int i = 0; i < CHUNK; i++) pos += (i < tid) && (rank[i] < m);
        sl[pos] = tid;
        unsigned hu = (unsigned)(keys[c * CHUNK + tid] >> 32);
        unsigned orig = (hu & 0x80000000u) ? (hu ^ 0x80000000u) : ~hu;
        slw[pos] = __uint_as_float(orig);
    }
    int ns = __syncthreads_count(selme);                      // barrier #3

    // ---- Phase 4: gather selected rows, 2 s-subgroups
    const int jsub = tid / S;          // 0,1 active; tid >= 392 idle
    const int s    = tid - jsub * S;
    if (jsub < 2) {
        const float* base = attns + ((size_t)(LAYER_ID * B + b)) * H * T * S + s;
        float acc = 0.f;
        for (int i = jsub; i < ns; i += 4) {   // handles i and i+2 per iter
            int i2 = i + 2;
            bool a2 = (i2 < ns);
            int   t0i = c * CHUNK + sl[i];
            int   t1i = a2 ? (c * CHUNK + sl[i2]) : t0i;
            float w0  = slw[i];
            float w1  = a2 ? slw[i2] : 0.f;
            const float* p0 = base + (size_t)t0i * S;
            const float* p1 = base + (size_t)t1i * S;
            float v0[8], v1[8];
#pragma unroll
            for (int h = 0; h < H; h++) {
                v0[h] = __ldg(p0 + (size_t)h * T * S);
                v1[h] = __ldg(p1 + (size_t)h * T * S);
            }
            float h0 = 0.f, h1 = 0.f;
#pragma unroll
            for (int h = 0; h < H; h++) { h0 += v0[h]; h1 += v1[h]; }
            acc += fmaxf(w0 * (h0 * 0.125f), 0.f);
            if (a2) acc += fmaxf(w1 * (h1 * 0.125f), 0.f);
        }
        g_part[b][c * 2 + jsub][s] = acc;
    }

    // ---- Phase 5: arrival; last block per b merges + normalizes
    __threadfence();
    __syncthreads();
    if (tid == 0) {
        int done = atomicAdd(&g_sync[b], 1);
        s_last = (done == NBLK - 1);
    }
    __syncthreads();
    if (!s_last) return;
    if (tid == 0) g_sync[b] = 0;       // reset for next graph replay
    __threadfence();

    float acc = 0.f;
    const bool active = (tid < S);
    if (active) {
#pragma unroll
        for (int g2 = 0; g2 < NG; g2++) acc += ldcg(&g_part[b][g2][tid]);
        acc /= (float)m;
    }
    if (tid < 256) {
        rmin[tid] = active ? acc :  CUDART_INF_F;
        rmax[tid] = active ? acc : -CUDART_INF_F;
    }
    __syncthreads();
    for (int o = 128; o > 0; o >>= 1) {
        if (tid < o) {
            rmin[tid] = fminf(rmin[tid], rmin[tid + o]);
            rmax[tid] = fmaxf(rmax[tid], rmax[tid + o]);
        }
        __syncthreads();
    }
    if (tid == 0) { s_mn = rmin[0]; s_mx = rmax[0]; }
    __syncthreads();

    if (active)
        out[b * S + tid] = (acc - s_mn) / fmaxf(s_mx - s_mn, 1e-12f);
}

// ---------------------------------------------------------------------------
extern "C" void kernel_launch(void* const* d_in, const int* in_sizes, int n_in,
                              void* d_out, int out_size)
{
    const float* fore    = (const float*)d_in[0];  // (B, D)
    const float* embed   = (const float*)d_in[1];  // (B, T, D)
    const float* attns   = (const float*)d_in[2];  // (L, B, H, T, S)
    const int*   targets = (const int*)  d_in[3];  // (B, T+1) int32
    float* out = (float*)d_out;

    k_weights<<<dim3(T / 16, B), 256>>>(fore, embed, targets);
    k_fused<<<dim3(NBLK, B), 512>>>(targets, attns, out);
}

// round 10
// speedup vs baseline: 1.8224x; 1.8224x over previous
#include <cuda_runtime.h>
#include <math_constants.h>

// Shapes (fixed by problem)
#define B 32
#define T 512
#define D 512
#define H 8
#define S 196
#define LAYER_ID 2
#define K_TOP 51   // int(0.1 * 512)
#define NBLK 16    // blocks per batch
#define CHUNK 32   // t's per block
#define NG 32      // partial groups (NBLK x 2 subgroups)

// Scratch (allocation-free rule: __device__ globals; zero-initialized)
__device__ float g_w[B * T];
__device__ float g_part[B][NG][S];
__device__ int   g_sync[B];

__device__ __forceinline__ float ldcg(const float* p) {
    float v; asm volatile("ld.global.cg.f32 %0, [%1];" : "=f"(v) : "l"(p));
    return v;
}

// ---------------------------------------------------------------------------
// Kernel 1: cosine weights. One warp handles TWO t-rows (12 LDG.128/thread),
// no smem, no syncthreads. grid (T/16, B), 256 threads.  [validated R6]
// ---------------------------------------------------------------------------
__global__ __launch_bounds__(256) void k_weights(
    const float* __restrict__ fore,     // (B, D)
    const float* __restrict__ embed,    // (B, T, D)
    const int*   __restrict__ targets)  // (B, T+1) int32
{
    const int b    = blockIdx.y;
    const int lane = threadIdx.x & 31;
    const int warp = threadIdx.x >> 5;
    const int t0   = (blockIdx.x * 8 + warp) * 2;

    const float4* yrow = reinterpret_cast<const float4*>(fore + (size_t)b * D);
    const float4* x0   = reinterpret_cast<const float4*>(embed + ((size_t)b * T + t0) * D);
    const float4* x1   = x0 + D / 4;

    float4 yv[4], xa[4], xb[4];
#pragma unroll
    for (int i = 0; i < 4; i++) {
        yv[i] = __ldg(&yrow[lane + i * 32]);
        xa[i] = __ldg(&x0[lane + i * 32]);
        xb[i] = __ldg(&x1[lane + i * 32]);
    }

    float n0 = 0.f, n1 = 0.f, xs0 = 0.f, xs1 = 0.f, ys = 0.f;
#pragma unroll
    for (int i = 0; i < 4; i++) {
        float4 y = yv[i], a = xa[i], c = xb[i];
        ys  += y.x * y.x + y.y * y.y + y.z * y.z + y.w * y.w;
        n0  += a.x * y.x + a.y * y.y + a.z * y.z + a.w * y.w;
        xs0 += a.x * a.x + a.y * a.y + a.z * a.z + a.w * a.w;
        n1  += c.x * y.x + c.y * y.y + c.z * y.z + c.w * y.w;
        xs1 += c.x * c.x + c.y * c.y + c.z * c.z + c.w * c.w;
    }
#pragma unroll
    for (int o = 16; o; o >>= 1) {
        n0  += __shfl_xor_sync(0xffffffffu, n0,  o);
        n1  += __shfl_xor_sync(0xffffffffu, n1,  o);
        xs0 += __shfl_xor_sync(0xffffffffu, xs0, o);
        xs1 += __shfl_xor_sync(0xffffffffu, xs1, o);
        ys  += __shfl_xor_sync(0xffffffffu, ys,  o);
    }
    if (lane < 2) {
        const int t = t0 + lane;
        float num = lane ? n1 : n0;
        float xn2 = lane ? xs1 : xs0;
        float xn  = fmaxf(sqrtf(xn2), 1e-8f);
        float yn  = fmaxf(sqrtf(ys),  1e-8f);
        float w   = num / (xn * yn);
        int tv    = targets[b * (T + 1) + t];
        bool msk  = (t == 0) || (tv > 0);
        g_w[b * T + t] = msk ? w : -1.0f;
    }
}

// ---------------------------------------------------------------------------
// Kernel 2 (fused): grid (NBLK, B), 512 threads. Block c ranks ONLY its
// 32-t chunk. Layout: tl = lane (tid&31), piece = warp (tid>>5) -> all lanes
// of a warp scan the SAME 32-key slice (LDS broadcast, conflict-free, same
// pattern as R6), each lane owns one t-local; 16 per-warp partials combined
// with atomicAdd (spread addresses). Select rank<m, gather selected rows
// (2 s-subgroups); last-arriving block per b merges 32 partials + normalizes.
// ---------------------------------------------------------------------------
__global__ __launch_bounds__(512) void k_fused(
    const int*   __restrict__ targets,  // (B, T+1) int32
    const float* __restrict__ attns,    // (L, B, H, T, S)
    float*       __restrict__ out)      // (B, S)
{
    __shared__ unsigned long long keys[T];   // 4 KB
    __shared__ int   rank[CHUNK];
    __shared__ int   sl[CHUNK];
    __shared__ float slw[CHUNK];
    __shared__ int   s_last;
    __shared__ float rmin[256], rmax[256];
    __shared__ float s_mn, s_mx;

    const int c   = blockIdx.x;   // 0..NBLK-1
    const int b   = blockIdx.y;
    const int tid = threadIdx.x;  // 0..511

    // ---- Phase 1: keys (order-preserving map, index tie-break) + m
    float w = ldcg(&g_w[b * T + tid]);
    unsigned uf = __float_as_uint(w);
    uf = (uf & 0x80000000u) ? ~uf : (uf | 0x80000000u);
    keys[tid] = ((unsigned long long)uf << 32) | (unsigned)(T - 1 - tid);
    if (tid < CHUNK) rank[tid] = 0;

    int tv  = targets[b * (T + 1) + tid];
    int cnt = __syncthreads_count((tid == 0) || (tv > 0));   // barrier #1
    int m   = (int)ceilf((float)cnt * 0.1f);
    m = m < K_TOP ? m : K_TOP;

    // ---- Phase 2: chunk-local rank counting, broadcast LDS, warp-owned slice
    {
        const int tl    = tid & 31;                // lane = t_local
        const int piece = tid >> 5;                // warp = key slice
        const unsigned long long mykey = keys[c * CHUNK + tl];
        const unsigned long long* kp = keys + piece * 32;
        int r = 0;
#pragma unroll
        for (int i = 0; i < 32; i++) r += (kp[i] > mykey);   // broadcast reads
        atomicAdd(&rank[tl], r);                   // 32 spread addrs/warp
    }
    __syncthreads();                                          // barrier #2

    // ---- Phase 3: selected list for this chunk, t-order (deterministic)
    bool selme = (tid < CHUNK) && (rank[tid] < m);
    if (selme) {
        int pos = 0;
#pragma unroll
        for (int i = 0; i < CHUNK; i++) pos += (i < tid) && (rank[i] < m);
        sl[pos] = tid;
        unsigned hu = (unsigned)(keys[c * CHUNK + tid] >> 32);
        unsigned orig = (hu & 0x80000000u) ? (hu ^ 0x80000000u) : ~hu;
        slw[pos] = __uint_as_float(orig);
    }
    int ns = __syncthreads_count(selme);                      // barrier #3

    // ---- Phase 4: gather selected rows, 2 s-subgroups
    const int jsub = tid / S;          // 0,1 active; tid >= 392 idle
    const int s    = tid - jsub * S;
    if (jsub < 2) {
        const float* base = attns + ((size_t)(LAYER_ID * B + b)) * H * T * S + s;
        float acc = 0.f;
        for (int i = jsub; i < ns; i += 4) {   // handles i and i+2 per iter
            int i2 = i + 2;
            bool a2 = (i2 < ns);
            int   t0i = c * CHUNK + sl[i];
            int   t1i = a2 ? (c * CHUNK + sl[i2]) : t0i;
            float w0  = slw[i];
            float w1  = a2 ? slw[i2] : 0.f;
            const float* p0 = base + (size_t)t0i * S;
            const float* p1 = base + (size_t)t1i * S;
            float v0[8], v1[8];
#pragma unroll
            for (int h = 0; h < H; h++) {
                v0[h] = __ldg(p0 + (size_t)h * T * S);
                v1[h] = __ldg(p1 + (size_t)h * T * S);
            }
            float h0 = 0.f, h1 = 0.f;
#pragma unroll
            for (int h = 0; h < H; h++) { h0 += v0[h]; h1 += v1[h]; }
            acc += fmaxf(w0 * (h0 * 0.125f), 0.f);
            if (a2) acc += fmaxf(w1 * (h1 * 0.125f), 0.f);
        }
        g_part[b][c * 2 + jsub][s] = acc;
    }

    // ---- Phase 5: arrival; last block per b merges + normalizes
    __threadfence();
    __syncthreads();
    if (tid == 0) {
        int done = atomicAdd(&g_sync[b], 1);
        s_last = (done == NBLK - 1);
    }
    __syncthreads();
    if (!s_last) return;
    if (tid == 0) g_sync[b] = 0;       // reset for next graph replay
    __threadfence();

    float acc = 0.f;
    const bool active = (tid < S);
    if (active) {
#pragma unroll
        for (int g2 = 0; g2 < NG; g2++) acc += ldcg(&g_part[b][g2][tid]);
        acc /= (float)m;
    }
    if (tid < 256) {
        rmin[tid] = active ? acc :  CUDART_INF_F;
        rmax[tid] = active ? acc : -CUDART_INF_F;
    }
    __syncthreads();
    for (int o = 128; o > 0; o >>= 1) {
        if (tid < o) {
            rmin[tid] = fminf(rmin[tid], rmin[tid + o]);
            rmax[tid] = fmaxf(rmax[tid], rmax[tid + o]);
        }
        __syncthreads();
    }
    if (tid == 0) { s_mn = rmin[0]; s_mx = rmax[0]; }
    __syncthreads();

    if (active)
        out[b * S + tid] = (acc - s_mn) / fmaxf(s_mx - s_mn, 1e-12f);
}

// ---------------------------------------------------------------------------
extern "C" void kernel_launch(void* const* d_in, const int* in_sizes, int n_in,
                              void* d_out, int out_size)
{
    const float* fore    = (const float*)d_in[0];  // (B, D)
    const float* embed   = (const float*)d_in[1];  // (B, T, D)
    const float* attns   = (const float*)d_in[2];  // (L, B, H, T, S)
    const int*   targets = (const int*)  d_in[3];  // (B, T+1) int32
    float* out = (float*)d_out;

    k_weights<<<dim3(T / 16, B), 256>>>(fore, embed, targets);
    k_fused<<<dim3(NBLK, B), 512>>>(targets, attns, out);
}